// round 13
// baseline (speedup 1.0000x reference)
#include <cuda_runtime.h>

#define H 1024
#define SEQ 2048
#define VOC 50257
#define LSE_BLOCKS 32

// ---------------- device scratch (static, allocation-guard safe) ----------------
// Biases are pre-folded into these partials by the GEMV kernels.
__device__ __align__(16) float g_gi0[3 * H];
__device__ __align__(16) float g_gh0[3 * H];
__device__ __align__(16) float g_gi1[3 * H];
__device__ __align__(16) float g_gh1[3 * H];
__device__ __align__(16) float g_h1[H];
__device__ __align__(16) float g_v[H];
__device__ float g_c;
__device__ __align__(16) float g_scores[SEQ];
__device__ __align__(16) float g_attn[SEQ];
__device__ __align__(16) float g_vpart[64 * H];
__device__ __align__(16) float g_cpart[64 * H];
__device__ __align__(16) float g_context[H];
__device__ __align__(16) float g_logits[VOC];
__device__ __align__(16) float g_logits2[VOC];
__device__ float g_lse_m[LSE_BLOCKS];
__device__ float g_lse_s[LSE_BLOCKS];
__device__ float g_logZ;
__device__ unsigned g_cnt;
__device__ unsigned g_flag;
__device__ unsigned g_done;
__device__ unsigned g_h1flag;
__device__ unsigned g_h1done;

__device__ __forceinline__ float warp_sum(float v) {
    #pragma unroll
    for (int o = 16; o; o >>= 1) v += __shfl_xor_sync(0xffffffffu, v, o);
    return v;
}
__device__ __forceinline__ float warp_max(float v) {
    #pragma unroll
    for (int o = 16; o; o >>= 1) v = fmaxf(v, __shfl_xor_sync(0xffffffffu, v, o));
    return v;
}

// h1 gate from bias-folded partials (pure; identical everywhere -> consistent values)
__device__ __forceinline__ float h1_gate(int j, const float* __restrict__ last_hidden) {
    float r = 1.f / (1.f + expf(-(g_gi1[j] + g_gh1[j])));
    float z = 1.f / (1.f + expf(-(g_gi1[j + H] + g_gh1[j + H])));
    float n = tanhf(g_gi1[j + 2 * H] + r * g_gh1[j + 2 * H]);
    return (1.f - z) * n + z * last_hidden[H + j];
}

__global__ void k_warm() {}

// ---------------- GRU kernel A: all input-only GEMV rows, biases folded ----------------
__global__ void k_gru_a(const int* __restrict__ word,
                        const float* __restrict__ emb,
                        const float* __restrict__ last_context,
                        const float* __restrict__ W_ih0,
                        const float* __restrict__ W_hh0,
                        const float* __restrict__ W_hh1,
                        const float* __restrict__ last_hidden,
                        const float* __restrict__ b_ih0,
                        const float* __restrict__ b_hh0,
                        const float* __restrict__ b_hh1) {
    int w = (blockIdx.x * blockDim.x + threadIdx.x) >> 5;
    int lane = threadIdx.x & 31;

    if (w < 3 * H) {
        int w0 = word[0];
        const float4* emb4 = (const float4*)(emb + (size_t)w0 * H);
        const float4* ctx4 = (const float4*)last_context;
        const float4* row = (const float4*)(W_ih0 + (size_t)w * (2 * H));
        float acc = 0.f;
        #pragma unroll
        for (int t = 0; t < 8; t++) {
            int i = lane + t * 32;
            float4 a = row[i];
            float4 x = emb4[i];
            acc += x.x * a.x + x.y * a.y + x.z * a.z + x.w * a.w;
        }
        #pragma unroll
        for (int t = 8; t < 16; t++) {
            int i = lane + t * 32;
            float4 a = row[i];
            float4 x = ctx4[i - 256];
            acc += x.x * a.x + x.y * a.y + x.z * a.z + x.w * a.w;
        }
        acc = warp_sum(acc);
        if (lane == 0) g_gi0[w] = acc + b_ih0[w];
    } else if (w < 6 * H) {
        int r = w - 3 * H;
        const float4* row = (const float4*)(W_hh0 + (size_t)r * H);
        const float4* hv = (const float4*)last_hidden;
        float acc = 0.f;
        #pragma unroll
        for (int t = 0; t < 8; t++) {
            int i = lane + t * 32;
            float4 a = row[i];
            float4 x = hv[i];
            acc += x.x * a.x + x.y * a.y + x.z * a.z + x.w * a.w;
        }
        acc = warp_sum(acc);
        if (lane == 0) g_gh0[r] = acc + b_hh0[r];
    } else {
        int r = w - 6 * H;
        const float4* row = (const float4*)(W_hh1 + (size_t)r * H);
        const float4* hv = (const float4*)(last_hidden + H);
        float acc = 0.f;
        #pragma unroll
        for (int t = 0; t < 8; t++) {
            int i = lane + t * 32;
            float4 a = row[i];
            float4 x = hv[i];
            acc += x.x * a.x + x.y * a.y + x.z * a.z + x.w * a.w;
        }
        acc = warp_sum(acc);
        if (lane == 0) g_gh1[r] = acc + b_hh1[r];
    }
}

// ---------------- GRU kernel B: W-row loads hoisted above h0 combine ----------------
// 96 blocks x 1024 threads. DRAM row loads issue first; gate combine + sync hide them.
__global__ void k_gru_b(const float* __restrict__ W_ih1,
                        const float* __restrict__ b_ih1,
                        const float* __restrict__ last_hidden,
                        float* __restrict__ out_h0) {
    __shared__ __align__(16) float h0sh[H];
    int tid = threadIdx.x;  // 1024
    int w = blockIdx.x * 32 + (tid >> 5);
    int lane = tid & 31;

    // 1) issue all 8 independent W-row loads (no dependence on h0)
    const float4* row = (const float4*)(W_ih1 + (size_t)w * H);
    float4 a0 = row[lane];
    float4 a1 = row[lane + 32];
    float4 a2 = row[lane + 64];
    float4 a3 = row[lane + 96];
    float4 a4 = row[lane + 128];
    float4 a5 = row[lane + 160];
    float4 a6 = row[lane + 192];
    float4 a7 = row[lane + 224];

    // 2) combine h0 (1 gate per thread) while loads are in flight
    {
        int j = tid;
        float r = 1.f / (1.f + expf(-(g_gi0[j] + g_gh0[j])));
        float z = 1.f / (1.f + expf(-(g_gi0[j + H] + g_gh0[j + H])));
        float n = tanhf(g_gi0[j + 2 * H] + r * g_gh0[j + 2 * H]);
        float ho = (1.f - z) * n + z * last_hidden[j];
        h0sh[j] = ho;
        if (blockIdx.x == 0) out_h0[j] = ho;
    }
    __syncthreads();

    // 3) dot with smem x
    const float4* xv = (const float4*)h0sh;
    float4 x0 = xv[lane];
    float4 x1 = xv[lane + 32];
    float4 x2 = xv[lane + 64];
    float4 x3 = xv[lane + 96];
    float4 x4 = xv[lane + 128];
    float4 x5 = xv[lane + 160];
    float4 x6 = xv[lane + 192];
    float4 x7 = xv[lane + 224];
    float acc = a0.x * x0.x + a0.y * x0.y + a0.z * x0.z + a0.w * x0.w
              + a1.x * x1.x + a1.y * x1.y + a1.z * x1.z + a1.w * x1.w
              + a2.x * x2.x + a2.y * x2.y + a2.z * x2.z + a2.w * x2.w
              + a3.x * x3.x + a3.y * x3.y + a3.z * x3.z + a3.w * x3.w
              + a4.x * x4.x + a4.y * x4.y + a4.z * x4.z + a4.w * x4.w
              + a5.x * x5.x + a5.y * x5.y + a5.z * x5.z + a5.w * x5.w
              + a6.x * x6.x + a6.y * x6.y + a6.z * x6.z + a6.w * x6.w
              + a7.x * x7.x + a7.y * x7.y + a7.z * x7.z + a7.w * x7.w;
    acc = warp_sum(acc);
    if (lane == 0) g_gi1[w] = acc + b_ih1[w];
}

// ---------------- v partials: inline 16-gate h1 recompute + weighted row-sum ----------------
__global__ void k_v_part(const float* __restrict__ Wa, const float* __restrict__ last_hidden) {
    __shared__ float hsh[16];
    int tid = threadIdx.x;  // 128
    int r0 = blockIdx.y * 16;
    if (tid < 16) hsh[tid] = h1_gate(r0 + tid, last_hidden);
    __syncthreads();
    int j = blockIdx.x * 128 + tid;
    float a0 = 0.f, a1 = 0.f, a2 = 0.f, a3 = 0.f;
    #pragma unroll
    for (int ss = 0; ss < 16; ss += 4) {
        a0 += hsh[ss + 0] * Wa[(size_t)(r0 + ss + 0) * H + j];
        a1 += hsh[ss + 1] * Wa[(size_t)(r0 + ss + 1) * H + j];
        a2 += hsh[ss + 2] * Wa[(size_t)(r0 + ss + 2) * H + j];
        a3 += hsh[ss + 3] * Wa[(size_t)(r0 + ss + 3) * H + j];
    }
    g_vpart[blockIdx.y * H + j] = (a0 + a1) + (a2 + a3);
}

// ---------------- v = reduce(vpart) ; c = ba.h1 (inline h1 recompute) ----------------
__global__ void k_v_reduce(const float* __restrict__ ba, const float* __restrict__ last_hidden) {
    int tid = threadIdx.x;  // 256
    if (blockIdx.x == 4) {
        float a = 0.f;
        #pragma unroll
        for (int t = 0; t < 4; t++) {
            int i = tid + t * 256;
            a += ba[i] * h1_gate(i, last_hidden);
        }
        a = warp_sum(a);
        __shared__ float red[8];
        if ((tid & 31) == 0) red[tid >> 5] = a;
        __syncthreads();
        if (tid == 0) {
            float s = 0.f;
            #pragma unroll
            for (int i = 0; i < 8; i++) s += red[i];
            g_c = s;
        }
        return;
    }
    int j = blockIdx.x * 256 + tid;
    float a = 0.f;
    #pragma unroll
    for (int y = 0; y < 64; y++) a += g_vpart[y * H + j];
    g_v[j] = a;
}

// ---------------- scores[s] = enc[s,:].v + c  (warp per s) ----------------
__global__ void k_scores(const float* __restrict__ enc) {
    int warp = (blockIdx.x * blockDim.x + threadIdx.x) >> 5;
    int lane = threadIdx.x & 31;
    if (warp >= SEQ) return;
    const float4* e = (const float4*)(enc + (size_t)warp * H);
    const float4* vv = (const float4*)g_v;
    float acc = 0.f;
    #pragma unroll
    for (int t = 0; t < H / 128; t++) {
        int i = lane + t * 32;
        float4 a = e[i];
        float4 b = vv[i];
        acc += a.x * b.x + a.y * b.y + a.z * b.z + a.w * b.w;
    }
    acc = warp_sum(acc);
    if (lane == 0) g_scores[warp] = acc + g_c;
}

// ---------------- softmax over 2048 scores (single block) ----------------
__global__ void k_softmax(float* __restrict__ out_attn) {
    __shared__ float red[32];
    __shared__ float bc;
    int tid = threadIdx.x;  // 1024

    float m = -1e30f;
    for (int s = tid; s < SEQ; s += 1024) m = fmaxf(m, g_scores[s]);
    m = warp_max(m);
    if ((tid & 31) == 0) red[tid >> 5] = m;
    __syncthreads();
    if (tid < 32) {
        float v = warp_max(red[tid]);
        if (tid == 0) bc = v;
    }
    __syncthreads();
    float M = bc;

    float sum = 0.f;
    for (int s = tid; s < SEQ; s += 1024) {
        float e = expf(g_scores[s] - M);
        g_attn[s] = e;
        sum += e;
    }
    sum = warp_sum(sum);
    if ((tid & 31) == 0) red[tid >> 5] = sum;
    __syncthreads();
    if (tid < 32) {
        float v = warp_sum(red[tid]);
        if (tid == 0) bc = 1.f / v;
    }
    __syncthreads();
    float inv = bc;
    for (int s = tid; s < SEQ; s += 1024) {
        float w = g_attn[s] * inv;
        g_attn[s] = w;
        out_attn[s] = w;
    }
}

// ---------------- context partials: 64 chunks of 32 rows (coalesced) ----------------
__global__ void k_ctx_part(const float* __restrict__ enc) {
    __shared__ float wsh[32];
    int tid = threadIdx.x;  // 128
    int s0 = blockIdx.y * 32;
    if (tid < 32) wsh[tid] = g_attn[s0 + tid];
    __syncthreads();
    int j = blockIdx.x * 128 + tid;
    float a0 = 0.f, a1 = 0.f, a2 = 0.f, a3 = 0.f;
    #pragma unroll
    for (int ss = 0; ss < 32; ss += 4) {
        a0 += wsh[ss + 0] * enc[(size_t)(s0 + ss + 0) * H + j];
        a1 += wsh[ss + 1] * enc[(size_t)(s0 + ss + 1) * H + j];
        a2 += wsh[ss + 2] * enc[(size_t)(s0 + ss + 2) * H + j];
        a3 += wsh[ss + 3] * enc[(size_t)(s0 + ss + 3) * H + j];
    }
    g_cpart[blockIdx.y * H + j] = (a0 + a1) + (a2 + a3);
}

// ---------------- reduce 64 partials -> context ----------------
__global__ void k_ctx_reduce(float* __restrict__ out_context) {
    int j = blockIdx.x * blockDim.x + threadIdx.x;
    if (j >= H) return;
    float a = 0.f;
    #pragma unroll
    for (int y = 0; y < 64; y++) a += g_cpart[y * H + j];
    g_context[j] = a;
    out_context[j] = a;
}

// ---------------- logits pass A: block 0 publishes h1, others spin-then-read ----------------
__global__ void k_logits_h1(const float* __restrict__ W_out, const float* __restrict__ b_out,
                            const float* __restrict__ last_hidden, float* __restrict__ out_h1) {
    __shared__ __align__(16) float u[H];
    int tid = threadIdx.x;  // 256

    if (blockIdx.x == 0) {
        #pragma unroll
        for (int t = 0; t < 4; t++) {
            int j = tid + t * 256;
            float ho = h1_gate(j, last_hidden);
            u[j] = ho;
            g_h1[j] = ho;
            out_h1[j] = ho;
        }
        __threadfence();   // release g_h1 before flag
        __syncthreads();
        if (tid == 0) atomicExch(&g_h1flag, 1u);
    } else {
        if (tid == 0) {
            while (atomicAdd(&g_h1flag, 0u) == 0u) { __nanosleep(32); }
        }
        __syncthreads();
        __threadfence();   // acquire g_h1
        for (int k = tid; k < H; k += 256) u[k] = g_h1[k];
        __syncthreads();
    }

    // reset protocol for graph replay: all blocks passed the flag; last one clears it
    if (tid == 0) {
        unsigned d = atomicAdd(&g_h1done, 1u);
        if (d == gridDim.x - 1) {
            g_h1done = 0;
            g_h1flag = 0;
        }
    }

    int r = blockIdx.x * 8 + (tid >> 5);
    if (r >= VOC) return;
    int lane = tid & 31;
    const float4* w = (const float4*)(W_out + (size_t)r * (2 * H));
    const float4* uv = (const float4*)u;
    float acc0 = 0.f, acc1 = 0.f;
    #pragma unroll
    for (int t = 0; t < 4; t++) {
        int i0 = lane + (2 * t) * 32;
        int i1 = lane + (2 * t + 1) * 32;
        float4 a = __ldcs(&w[i0]);
        float4 b = uv[i0];
        acc0 += a.x * b.x + a.y * b.y + a.z * b.z + a.w * b.w;
        float4 c = __ldcs(&w[i1]);
        float4 d = uv[i1];
        acc1 += c.x * d.x + c.y * d.y + c.z * d.z + c.w * d.w;
    }
    float acc = warp_sum(acc0 + acc1);
    if (lane == 0) g_logits[r] = acc + b_out[r];
}

// ---------------- logits pass B: W_out[:, H:] @ context -> g_logits2 ----------------
__global__ void k_logits_ctx(const float* __restrict__ W_out) {
    __shared__ __align__(16) float u[H];
    for (int k = threadIdx.x; k < H; k += 256) u[k] = g_context[k];
    __syncthreads();

    int r = blockIdx.x * 8 + (threadIdx.x >> 5);
    if (r >= VOC) return;
    int lane = threadIdx.x & 31;
    const float4* w = (const float4*)(W_out + (size_t)r * (2 * H) + H);
    const float4* uv = (const float4*)u;
    float acc0 = 0.f, acc1 = 0.f;
    #pragma unroll
    for (int t = 0; t < 4; t++) {
        int i0 = lane + (2 * t) * 32;
        int i1 = lane + (2 * t + 1) * 32;
        float4 a = __ldcs(&w[i0]);
        float4 b = uv[i0];
        acc0 += a.x * b.x + a.y * b.y + a.z * b.z + a.w * b.w;
        float4 c = __ldcs(&w[i1]);
        float4 d = uv[i1];
        acc1 += c.x * d.x + c.y * d.y + c.z * d.z + c.w * d.w;
    }
    float acc = warp_sum(acc0 + acc1);
    if (lane == 0) g_logits2[r] = acc;
}

// ---------------- fused lse + output: 32 resident blocks, ticket + flag ----------------
__global__ void k_lse_out(float* __restrict__ out) {
    __shared__ float red[8];
    __shared__ float bc;
    int tid = threadIdx.x;  // 256
    const int chunk = (VOC + LSE_BLOCKS - 1) / LSE_BLOCKS;
    int lo = blockIdx.x * chunk;
    int hi = min(lo + chunk, VOC);

    float m = -1e30f;
    for (int r = lo + tid; r < hi; r += 256) m = fmaxf(m, g_logits[r] + g_logits2[r]);
    m = warp_max(m);
    if ((tid & 31) == 0) red[tid >> 5] = m;
    __syncthreads();
    if (tid < 32) {
        float v = (tid < 8) ? red[tid] : -1e30f;
        v = warp_max(v);
        if (tid == 0) bc = v;
    }
    __syncthreads();
    float M = bc;

    float sum = 0.f;
    for (int r = lo + tid; r < hi; r += 256) sum += expf(g_logits[r] + g_logits2[r] - M);
    sum = warp_sum(sum);
    if ((tid & 31) == 0) red[tid >> 5] = sum;
    __syncthreads();
    if (tid < 32) {
        float v = (tid < 8) ? red[tid] : 0.f;
        v = warp_sum(v);
        if (tid == 0) {
            g_lse_m[blockIdx.x] = M;
            g_lse_s[blockIdx.x] = v;
        }
    }

    __threadfence();
    __syncthreads();
    if (tid == 0) {
        unsigned t = atomicAdd(&g_cnt, 1u);
        if (t == LSE_BLOCKS - 1) {
            __threadfence();
            float Mg = -1e30f;
            #pragma unroll
            for (int i = 0; i < LSE_BLOCKS; i++) Mg = fmaxf(Mg, g_lse_m[i]);
            float Z = 0.f;
            #pragma unroll
            for (int i = 0; i < LSE_BLOCKS; i++) Z += g_lse_s[i] * expf(g_lse_m[i] - Mg);
            g_logZ = Mg + logf(Z);
            __threadfence();
            atomicExch(&g_flag, 1u);
        }
        while (atomicAdd(&g_flag, 0u) == 0u) { __nanosleep(64); }
    }
    __syncthreads();
    __threadfence();
    float lz = g_logZ;

    for (int r = lo + tid; r < hi; r += 256) {
        out[r] = g_logits[r] + g_logits2[r] - lz;
    }

    __syncthreads();
    if (tid == 0) {
        __threadfence();
        unsigned d = atomicAdd(&g_done, 1u);
        if (d == LSE_BLOCKS - 1) {
            g_cnt = 0;
            g_done = 0;
            g_flag = 0;
        }
    }
}

// ---------------- stream/event setup (static ctor: pre-baseline, pre-capture) ----------------
static cudaStream_t g_s1;
static cudaEvent_t g_e1, g_e2;

namespace {
struct StreamInit {
    StreamInit() {
        cudaStreamCreateWithFlags(&g_s1, cudaStreamNonBlocking);
        cudaEventCreateWithFlags(&g_e1, cudaEventDisableTiming);
        cudaEventCreateWithFlags(&g_e2, cudaEventDisableTiming);
        k_warm<<<1, 32>>>();
        k_warm<<<1, 32, 0, g_s1>>>();
        cudaEventRecord(g_e1, 0);
        cudaEventRecord(g_e2, g_s1);
        cudaDeviceSynchronize();
    }
};
StreamInit g_stream_init;
}

// ---------------- launch ----------------
extern "C" void kernel_launch(void* const* d_in, const int* in_sizes, int n_in,
                              void* d_out, int out_size) {
    const int*   word         = (const int*)  d_in[0];
    const float* last_context = (const float*)d_in[1];
    const float* last_hidden  = (const float*)d_in[2];
    const float* enc          = (const float*)d_in[3];
    const float* emb          = (const float*)d_in[4];
    const float* W_ih0        = (const float*)d_in[5];
    const float* W_hh0        = (const float*)d_in[6];
    const float* b_ih0        = (const float*)d_in[7];
    const float* b_hh0        = (const float*)d_in[8];
    const float* W_ih1        = (const float*)d_in[9];
    const float* W_hh1        = (const float*)d_in[10];
    const float* b_ih1        = (const float*)d_in[11];
    const float* b_hh1        = (const float*)d_in[12];
    const float* Wa           = (const float*)d_in[13];
    const float* ba           = (const float*)d_in[14];
    const float* W_out        = (const float*)d_in[15];
    const float* b_out        = (const float*)d_in[16];
    float* out = (float*)d_out;

    // d_out layout: [output VOC | context H | hidden 2H | attn SEQ]
    float* out_context = out + VOC;
    float* out_h0      = out + VOC + H;
    float* out_h1      = out + VOC + 2 * H;
    float* out_attn    = out + VOC + 3 * H;

    // GRU chain: 2 serial kernels (h0 combine folded into gru_b; h1 folded into consumers)
    k_gru_a<<<1152, 256>>>(word, emb, last_context, W_ih0, W_hh0, W_hh1,
                           last_hidden, b_ih0, b_hh0, b_hh1);
    k_gru_b<<<96, 1024>>>(W_ih1, b_ih1, last_hidden, out_h0);

    // Fork: attention chain + logits_ctx on side stream (consumers recompute h1 inline)
    cudaEventRecord(g_e1, 0);
    cudaStreamWaitEvent(g_s1, g_e1, 0);

    {
        dim3 g(8, 64);
        k_v_part<<<g, 128, 0, g_s1>>>(Wa, last_hidden);
    }
    k_v_reduce<<<5, 256, 0, g_s1>>>(ba, last_hidden);
    k_scores<<<SEQ / 8, 256, 0, g_s1>>>(enc);
    k_softmax<<<1, 1024, 0, g_s1>>>(out_attn);
    {
        dim3 g(8, 64);
        k_ctx_part<<<g, 128, 0, g_s1>>>(enc);
    }
    k_ctx_reduce<<<4, 256, 0, g_s1>>>(out_context);
    k_logits_ctx<<<(VOC + 7) / 8, 256, 0, g_s1>>>(W_out);
    cudaEventRecord(g_e2, g_s1);

    // Main stream: logits pass A starts right after gru_b (block 0 publishes h1)
    k_logits_h1<<<(VOC + 7) / 8, 256>>>(W_out, b_out, last_hidden, out_h1);

    // Join, then fused log-softmax + output
    cudaStreamWaitEvent(0, g_e2, 0);
    k_lse_out<<<LSE_BLOCKS, 256>>>(out);
}

// round 14
// speedup vs baseline: 1.1063x; 1.1063x over previous
#include <cuda_runtime.h>

#define H 1024
#define SEQ 2048
#define VOC 50257
#define LSE_BLOCKS 32

// ---------------- device scratch (static, allocation-guard safe) ----------------
// Biases are pre-folded into these partials by the GEMV kernels.
__device__ __align__(16) float g_gi0[3 * H];
__device__ __align__(16) float g_gh0[3 * H];
__device__ __align__(16) float g_gh1[3 * H];
__device__ __align__(16) float g_h1[H];
__device__ __align__(16) float g_v[H];
__device__ float g_c;
__device__ __align__(16) float g_scores[SEQ];
__device__ __align__(16) float g_attn[SEQ];
__device__ __align__(16) float g_vpart[64 * H];
__device__ __align__(16) float g_cpart[64 * H];
__device__ __align__(16) float g_context[H];
__device__ __align__(16) float g_logits[VOC];
__device__ __align__(16) float g_logits2[VOC];
__device__ float g_lse_m[LSE_BLOCKS];
__device__ float g_lse_s[LSE_BLOCKS];
__device__ float g_logZ;
__device__ unsigned g_cnt;
__device__ unsigned g_flag;
__device__ unsigned g_done;

__device__ __forceinline__ float warp_sum(float v) {
    #pragma unroll
    for (int o = 16; o; o >>= 1) v += __shfl_xor_sync(0xffffffffu, v, o);
    return v;
}
__device__ __forceinline__ float warp_max(float v) {
    #pragma unroll
    for (int o = 16; o; o >>= 1) v = fmaxf(v, __shfl_xor_sync(0xffffffffu, v, o));
    return v;
}

__global__ void k_warm() {}

// ---------------- GRU kernel A: all input-only GEMV rows, biases folded ----------------
__global__ void k_gru_a(const int* __restrict__ word,
                        const float* __restrict__ emb,
                        const float* __restrict__ last_context,
                        const float* __restrict__ W_ih0,
                        const float* __restrict__ W_hh0,
                        const float* __restrict__ W_hh1,
                        const float* __restrict__ last_hidden,
                        const float* __restrict__ b_ih0,
                        const float* __restrict__ b_hh0,
                        const float* __restrict__ b_hh1) {
    int w = (blockIdx.x * blockDim.x + threadIdx.x) >> 5;
    int lane = threadIdx.x & 31;

    if (w < 3 * H) {
        int w0 = word[0];
        const float4* emb4 = (const float4*)(emb + (size_t)w0 * H);
        const float4* ctx4 = (const float4*)last_context;
        const float4* row = (const float4*)(W_ih0 + (size_t)w * (2 * H));
        float acc = 0.f;
        #pragma unroll
        for (int t = 0; t < 8; t++) {
            int i = lane + t * 32;
            float4 a = row[i];
            float4 x = emb4[i];
            acc += x.x * a.x + x.y * a.y + x.z * a.z + x.w * a.w;
        }
        #pragma unroll
        for (int t = 8; t < 16; t++) {
            int i = lane + t * 32;
            float4 a = row[i];
            float4 x = ctx4[i - 256];
            acc += x.x * a.x + x.y * a.y + x.z * a.z + x.w * a.w;
        }
        acc = warp_sum(acc);
        if (lane == 0) g_gi0[w] = acc + b_ih0[w];
    } else if (w < 6 * H) {
        int r = w - 3 * H;
        const float4* row = (const float4*)(W_hh0 + (size_t)r * H);
        const float4* hv = (const float4*)last_hidden;
        float acc = 0.f;
        #pragma unroll
        for (int t = 0; t < 8; t++) {
            int i = lane + t * 32;
            float4 a = row[i];
            float4 x = hv[i];
            acc += x.x * a.x + x.y * a.y + x.z * a.z + x.w * a.w;
        }
        acc = warp_sum(acc);
        if (lane == 0) g_gh0[r] = acc + b_hh0[r];
    } else {
        int r = w - 6 * H;
        const float4* row = (const float4*)(W_hh1 + (size_t)r * H);
        const float4* hv = (const float4*)(last_hidden + H);
        float acc = 0.f;
        #pragma unroll
        for (int t = 0; t < 8; t++) {
            int i = lane + t * 32;
            float4 a = row[i];
            float4 x = hv[i];
            acc += x.x * a.x + x.y * a.y + x.z * a.z + x.w * a.w;
        }
        acc = warp_sum(acc);
        if (lane == 0) g_gh1[r] = acc + b_hh1[r];
    }
}

// ---------------- GRU kernel B: h0 combine + full row-triple per warp -> h1 directly ----------------
// 128 blocks x 256 threads. Each block: h0 into smem (4 gates/thread), then each of its
// 8 warps computes all three W_ih1 gate-rows for ONE output j and lane 0 emits h1[j].
// No cross-block dependency: g_gh1 is ready from k_gru_a.
__global__ void k_gru_b(const float* __restrict__ W_ih1,
                        const float* __restrict__ b_ih1,
                        const float* __restrict__ last_hidden,
                        float* __restrict__ out_h0,
                        float* __restrict__ out_h1) {
    __shared__ __align__(16) float h0sh[H];
    int tid = threadIdx.x;  // 256

    // h0 combine: 4 gates per thread from L2-hot bias-folded partials
    #pragma unroll
    for (int t = 0; t < 4; t++) {
        int j = tid + t * 256;
        float r = 1.f / (1.f + expf(-(g_gi0[j] + g_gh0[j])));
        float z = 1.f / (1.f + expf(-(g_gi0[j + H] + g_gh0[j + H])));
        float n = tanhf(g_gi0[j + 2 * H] + r * g_gh0[j + 2 * H]);
        float ho = (1.f - z) * n + z * last_hidden[j];
        h0sh[j] = ho;
        if (blockIdx.x == 0) out_h0[j] = ho;
    }
    __syncthreads();

    int j = blockIdx.x * 8 + (tid >> 5);  // output index 0..1023
    int lane = tid & 31;
    const float4* rowr = (const float4*)(W_ih1 + (size_t)j * H);
    const float4* rowz = (const float4*)(W_ih1 + (size_t)(j + H) * H);
    const float4* rown = (const float4*)(W_ih1 + (size_t)(j + 2 * H) * H);
    const float4* xv = (const float4*)h0sh;

    float ar = 0.f, az = 0.f, an = 0.f;
    #pragma unroll
    for (int t = 0; t < 8; t++) {
        int i = lane + t * 32;
        float4 x = xv[i];
        float4 a = rowr[i];
        float4 b = rowz[i];
        float4 c = rown[i];
        ar += x.x * a.x + x.y * a.y + x.z * a.z + x.w * a.w;
        az += x.x * b.x + x.y * b.y + x.z * b.z + x.w * b.w;
        an += x.x * c.x + x.y * c.y + x.z * c.z + x.w * c.w;
    }
    ar = warp_sum(ar);
    az = warp_sum(az);
    an = warp_sum(an);

    if (lane == 0) {
        float gr = ar + b_ih1[j] + g_gh1[j];
        float gz = az + b_ih1[j + H] + g_gh1[j + H];
        float r = 1.f / (1.f + expf(-gr));
        float z = 1.f / (1.f + expf(-gz));
        float n = tanhf(an + b_ih1[j + 2 * H] + r * g_gh1[j + 2 * H]);
        float h = (1.f - z) * n + z * last_hidden[H + j];
        g_h1[j] = h;
        out_h1[j] = h;
    }
}

// ---------------- v partials: weighted row-sum of Wa (coalesced) ----------------
__global__ void k_v_part(const float* __restrict__ Wa) {
    __shared__ float hsh[16];
    int tid = threadIdx.x;  // 128
    int r0 = blockIdx.y * 16;
    if (tid < 16) hsh[tid] = g_h1[r0 + tid];
    __syncthreads();
    int j = blockIdx.x * 128 + tid;
    float a0 = 0.f, a1 = 0.f, a2 = 0.f, a3 = 0.f;
    #pragma unroll
    for (int ss = 0; ss < 16; ss += 4) {
        a0 += hsh[ss + 0] * Wa[(size_t)(r0 + ss + 0) * H + j];
        a1 += hsh[ss + 1] * Wa[(size_t)(r0 + ss + 1) * H + j];
        a2 += hsh[ss + 2] * Wa[(size_t)(r0 + ss + 2) * H + j];
        a3 += hsh[ss + 3] * Wa[(size_t)(r0 + ss + 3) * H + j];
    }
    g_vpart[blockIdx.y * H + j] = (a0 + a1) + (a2 + a3);
}

// ---------------- v = reduce(vpart) ; c = ba.h1 ----------------
__global__ void k_v_reduce(const float* __restrict__ ba) {
    int tid = threadIdx.x;  // 256
    if (blockIdx.x == 4) {
        float a = 0.f;
        for (int i = tid; i < H; i += 256) a += ba[i] * g_h1[i];
        a = warp_sum(a);
        __shared__ float red[8];
        if ((tid & 31) == 0) red[tid >> 5] = a;
        __syncthreads();
        if (tid == 0) {
            float s = 0.f;
            #pragma unroll
            for (int i = 0; i < 8; i++) s += red[i];
            g_c = s;
        }
        return;
    }
    int j = blockIdx.x * 256 + tid;
    float a = 0.f;
    #pragma unroll
    for (int y = 0; y < 64; y++) a += g_vpart[y * H + j];
    g_v[j] = a;
}

// ---------------- scores[s] = enc[s,:].v + c  (warp per s) ----------------
__global__ void k_scores(const float* __restrict__ enc) {
    int warp = (blockIdx.x * blockDim.x + threadIdx.x) >> 5;
    int lane = threadIdx.x & 31;
    if (warp >= SEQ) return;
    const float4* e = (const float4*)(enc + (size_t)warp * H);
    const float4* vv = (const float4*)g_v;
    float acc = 0.f;
    #pragma unroll
    for (int t = 0; t < H / 128; t++) {
        int i = lane + t * 32;
        float4 a = e[i];
        float4 b = vv[i];
        acc += a.x * b.x + a.y * b.y + a.z * b.z + a.w * b.w;
    }
    acc = warp_sum(acc);
    if (lane == 0) g_scores[warp] = acc + g_c;
}

// ---------------- softmax over 2048 scores (single block) ----------------
__global__ void k_softmax(float* __restrict__ out_attn) {
    __shared__ float red[32];
    __shared__ float bc;
    int tid = threadIdx.x;  // 1024

    float m = -1e30f;
    for (int s = tid; s < SEQ; s += 1024) m = fmaxf(m, g_scores[s]);
    m = warp_max(m);
    if ((tid & 31) == 0) red[tid >> 5] = m;
    __syncthreads();
    if (tid < 32) {
        float v = warp_max(red[tid]);
        if (tid == 0) bc = v;
    }
    __syncthreads();
    float M = bc;

    float sum = 0.f;
    for (int s = tid; s < SEQ; s += 1024) {
        float e = expf(g_scores[s] - M);
        g_attn[s] = e;
        sum += e;
    }
    sum = warp_sum(sum);
    if ((tid & 31) == 0) red[tid >> 5] = sum;
    __syncthreads();
    if (tid < 32) {
        float v = warp_sum(red[tid]);
        if (tid == 0) bc = 1.f / v;
    }
    __syncthreads();
    float inv = bc;
    for (int s = tid; s < SEQ; s += 1024) {
        float w = g_attn[s] * inv;
        g_attn[s] = w;
        out_attn[s] = w;
    }
}

// ---------------- context partials: 64 chunks of 32 rows (coalesced) ----------------
__global__ void k_ctx_part(const float* __restrict__ enc) {
    __shared__ float wsh[32];
    int tid = threadIdx.x;  // 128
    int s0 = blockIdx.y * 32;
    if (tid < 32) wsh[tid] = g_attn[s0 + tid];
    __syncthreads();
    int j = blockIdx.x * 128 + tid;
    float a0 = 0.f, a1 = 0.f, a2 = 0.f, a3 = 0.f;
    #pragma unroll
    for (int ss = 0; ss < 32; ss += 4) {
        a0 += wsh[ss + 0] * enc[(size_t)(s0 + ss + 0) * H + j];
        a1 += wsh[ss + 1] * enc[(size_t)(s0 + ss + 1) * H + j];
        a2 += wsh[ss + 2] * enc[(size_t)(s0 + ss + 2) * H + j];
        a3 += wsh[ss + 3] * enc[(size_t)(s0 + ss + 3) * H + j];
    }
    g_cpart[blockIdx.y * H + j] = (a0 + a1) + (a2 + a3);
}

// ---------------- reduce 64 partials -> context ----------------
__global__ void k_ctx_reduce(float* __restrict__ out_context) {
    int j = blockIdx.x * blockDim.x + threadIdx.x;
    if (j >= H) return;
    float a = 0.f;
    #pragma unroll
    for (int y = 0; y < 64; y++) a += g_cpart[y * H + j];
    g_context[j] = a;
    out_context[j] = a;
}

// ---------------- logits pass A: W_out[:, :H] @ h1 + b_out -> g_logits ----------------
__global__ void k_logits_h1(const float* __restrict__ W_out, const float* __restrict__ b_out) {
    __shared__ __align__(16) float u[H];
    for (int k = threadIdx.x; k < H; k += 256) u[k] = g_h1[k];
    __syncthreads();

    int r = blockIdx.x * 8 + (threadIdx.x >> 5);
    if (r >= VOC) return;
    int lane = threadIdx.x & 31;
    const float4* w = (const float4*)(W_out + (size_t)r * (2 * H));
    const float4* uv = (const float4*)u;
    float acc0 = 0.f, acc1 = 0.f;
    #pragma unroll
    for (int t = 0; t < 4; t++) {
        int i0 = lane + (2 * t) * 32;
        int i1 = lane + (2 * t + 1) * 32;
        float4 a = __ldcs(&w[i0]);
        float4 b = uv[i0];
        acc0 += a.x * b.x + a.y * b.y + a.z * b.z + a.w * b.w;
        float4 c = __ldcs(&w[i1]);
        float4 d = uv[i1];
        acc1 += c.x * d.x + c.y * d.y + c.z * d.z + c.w * d.w;
    }
    float acc = warp_sum(acc0 + acc1);
    if (lane == 0) g_logits[r] = acc + b_out[r];
}

// ---------------- logits pass B: W_out[:, H:] @ context -> g_logits2 ----------------
__global__ void k_logits_ctx(const float* __restrict__ W_out) {
    __shared__ __align__(16) float u[H];
    for (int k = threadIdx.x; k < H; k += 256) u[k] = g_context[k];
    __syncthreads();

    int r = blockIdx.x * 8 + (threadIdx.x >> 5);
    if (r >= VOC) return;
    int lane = threadIdx.x & 31;
    const float4* w = (const float4*)(W_out + (size_t)r * (2 * H) + H);
    const float4* uv = (const float4*)u;
    float acc0 = 0.f, acc1 = 0.f;
    #pragma unroll
    for (int t = 0; t < 4; t++) {
        int i0 = lane + (2 * t) * 32;
        int i1 = lane + (2 * t + 1) * 32;
        float4 a = __ldcs(&w[i0]);
        float4 b = uv[i0];
        acc0 += a.x * b.x + a.y * b.y + a.z * b.z + a.w * b.w;
        float4 c = __ldcs(&w[i1]);
        float4 d = uv[i1];
        acc1 += c.x * d.x + c.y * d.y + c.z * d.z + c.w * d.w;
    }
    float acc = warp_sum(acc0 + acc1);
    if (lane == 0) g_logits2[r] = acc;
}

// ---------------- fused lse + output: 32 resident blocks, ticket + flag ----------------
__global__ void k_lse_out(float* __restrict__ out) {
    __shared__ float red[8];
    __shared__ float bc;
    int tid = threadIdx.x;  // 256
    const int chunk = (VOC + LSE_BLOCKS - 1) / LSE_BLOCKS;
    int lo = blockIdx.x * chunk;
    int hi = min(lo + chunk, VOC);

    float m = -1e30f;
    for (int r = lo + tid; r < hi; r += 256) m = fmaxf(m, g_logits[r] + g_logits2[r]);
    m = warp_max(m);
    if ((tid & 31) == 0) red[tid >> 5] = m;
    __syncthreads();
    if (tid < 32) {
        float v = (tid < 8) ? red[tid] : -1e30f;
        v = warp_max(v);
        if (tid == 0) bc = v;
    }
    __syncthreads();
    float M = bc;

    float sum = 0.f;
    for (int r = lo + tid; r < hi; r += 256) sum += expf(g_logits[r] + g_logits2[r] - M);
    sum = warp_sum(sum);
    if ((tid & 31) == 0) red[tid >> 5] = sum;
    __syncthreads();
    if (tid < 32) {
        float v = (tid < 8) ? red[tid] : 0.f;
        v = warp_sum(v);
        if (tid == 0) {
            g_lse_m[blockIdx.x] = M;
            g_lse_s[blockIdx.x] = v;
        }
    }

    __threadfence();
    __syncthreads();
    if (tid == 0) {
        unsigned t = atomicAdd(&g_cnt, 1u);
        if (t == LSE_BLOCKS - 1) {
            __threadfence();
            float Mg = -1e30f;
            #pragma unroll
            for (int i = 0; i < LSE_BLOCKS; i++) Mg = fmaxf(Mg, g_lse_m[i]);
            float Z = 0.f;
            #pragma unroll
            for (int i = 0; i < LSE_BLOCKS; i++) Z += g_lse_s[i] * expf(g_lse_m[i] - Mg);
            g_logZ = Mg + logf(Z);
            __threadfence();
            atomicExch(&g_flag, 1u);
        }
        while (atomicAdd(&g_flag, 0u) == 0u) { __nanosleep(64); }
    }
    __syncthreads();
    __threadfence();
    float lz = g_logZ;

    for (int r = lo + tid; r < hi; r += 256) {
        out[r] = g_logits[r] + g_logits2[r] - lz;
    }

    __syncthreads();
    if (tid == 0) {
        __threadfence();
        unsigned d = atomicAdd(&g_done, 1u);
        if (d == LSE_BLOCKS - 1) {
            g_cnt = 0;
            g_done = 0;
            g_flag = 0;
        }
    }
}

// ---------------- stream/event setup (static ctor: pre-baseline, pre-capture) ----------------
static cudaStream_t g_s1;
static cudaEvent_t g_e1, g_e2;

namespace {
struct StreamInit {
    StreamInit() {
        cudaStreamCreateWithFlags(&g_s1, cudaStreamNonBlocking);
        cudaEventCreateWithFlags(&g_e1, cudaEventDisableTiming);
        cudaEventCreateWithFlags(&g_e2, cudaEventDisableTiming);
        k_warm<<<1, 32>>>();
        k_warm<<<1, 32, 0, g_s1>>>();
        cudaEventRecord(g_e1, 0);
        cudaEventRecord(g_e2, g_s1);
        cudaDeviceSynchronize();
    }
};
StreamInit g_stream_init;
}

// ---------------- launch ----------------
extern "C" void kernel_launch(void* const* d_in, const int* in_sizes, int n_in,
                              void* d_out, int out_size) {
    const int*   word         = (const int*)  d_in[0];
    const float* last_context = (const float*)d_in[1];
    const float* last_hidden  = (const float*)d_in[2];
    const float* enc          = (const float*)d_in[3];
    const float* emb          = (const float*)d_in[4];
    const float* W_ih0        = (const float*)d_in[5];
    const float* W_hh0        = (const float*)d_in[6];
    const float* b_ih0        = (const float*)d_in[7];
    const float* b_hh0        = (const float*)d_in[8];
    const float* W_ih1        = (const float*)d_in[9];
    const float* W_hh1        = (const float*)d_in[10];
    const float* b_ih1        = (const float*)d_in[11];
    const float* b_hh1        = (const float*)d_in[12];
    const float* Wa           = (const float*)d_in[13];
    const float* ba           = (const float*)d_in[14];
    const float* W_out        = (const float*)d_in[15];
    const float* b_out        = (const float*)d_in[16];
    float* out = (float*)d_out;

    // d_out layout: [output VOC | context H | hidden 2H | attn SEQ]
    float* out_context = out + VOC;
    float* out_h0      = out + VOC + H;
    float* out_h1      = out + VOC + 2 * H;
    float* out_attn    = out + VOC + 3 * H;

    // GRU chain: 2 serial kernels; gru_b emits h0 AND h1 (row-triple per warp)
    k_gru_a<<<1152, 256>>>(word, emb, last_context, W_ih0, W_hh0, W_hh1,
                           last_hidden, b_ih0, b_hh0, b_hh1);
    k_gru_b<<<128, 256>>>(W_ih1, b_ih1, last_hidden, out_h0, out_h1);

    // Fork: attention chain + logits_ctx on side stream (g_h1 materialized by gru_b)
    cudaEventRecord(g_e1, 0);
    cudaStreamWaitEvent(g_s1, g_e1, 0);

    {
        dim3 g(8, 64);
        k_v_part<<<g, 128, 0, g_s1>>>(Wa);
    }
    k_v_reduce<<<5, 256, 0, g_s1>>>(ba);
    k_scores<<<SEQ / 8, 256, 0, g_s1>>>(enc);
    k_softmax<<<1, 1024, 0, g_s1>>>(out_attn);
    {
        dim3 g(8, 64);
        k_ctx_part<<<g, 128, 0, g_s1>>>(enc);
    }
    k_ctx_reduce<<<4, 256, 0, g_s1>>>(out_context);
    k_logits_ctx<<<(VOC + 7) / 8, 256, 0, g_s1>>>(W_out);
    cudaEventRecord(g_e2, g_s1);

    // Main stream: logits pass A starts right after gru_b
    k_logits_h1<<<(VOC + 7) / 8, 256>>>(W_out, b_out);

    // Join, then fused log-softmax + output
    cudaStreamWaitEvent(0, g_e2, 0);
    k_lse_out<<<LSE_BLOCKS, 256>>>(out);
}

// round 15
// speedup vs baseline: 1.1109x; 1.0042x over previous
#include <cuda_runtime.h>

#define H 1024
#define SEQ 2048
#define VOC 50257
#define LSE_BLOCKS 32

// ---------------- device scratch (static, allocation-guard safe) ----------------
// Biases are pre-folded into these partials by the GEMV kernels.
__device__ __align__(16) float g_gi0[3 * H];
__device__ __align__(16) float g_gh0[3 * H];
__device__ __align__(16) float g_gh1[3 * H];
__device__ __align__(16) float g_h1[H];
__device__ __align__(16) float g_v[H];
__device__ float g_c;
__device__ __align__(16) float g_scores[SEQ];
__device__ __align__(16) float g_attn[SEQ];
__device__ __align__(16) float g_vpart[64 * H];
__device__ __align__(16) float g_cpart[64 * H];
__device__ __align__(16) float g_context[H];
__device__ __align__(16) float g_logits[VOC];
__device__ __align__(16) float g_logits2[VOC];
__device__ float g_lse_m[LSE_BLOCKS];
__device__ float g_lse_s[LSE_BLOCKS];
__device__ float g_logZ;
__device__ unsigned g_cnt;
__device__ unsigned g_flag;
__device__ unsigned g_done;

__device__ __forceinline__ float warp_sum(float v) {
    #pragma unroll
    for (int o = 16; o; o >>= 1) v += __shfl_xor_sync(0xffffffffu, v, o);
    return v;
}
__device__ __forceinline__ float warp_max(float v) {
    #pragma unroll
    for (int o = 16; o; o >>= 1) v = fmaxf(v, __shfl_xor_sync(0xffffffffu, v, o));
    return v;
}

__global__ void k_warm() {}

// ---------------- GRU kernel A: all input-only GEMV rows, biases folded ----------------
__global__ void k_gru_a(const int* __restrict__ word,
                        const float* __restrict__ emb,
                        const float* __restrict__ last_context,
                        const float* __restrict__ W_ih0,
                        const float* __restrict__ W_hh0,
                        const float* __restrict__ W_hh1,
                        const float* __restrict__ last_hidden,
                        const float* __restrict__ b_ih0,
                        const float* __restrict__ b_hh0,
                        const float* __restrict__ b_hh1) {
    int w = (blockIdx.x * blockDim.x + threadIdx.x) >> 5;
    int lane = threadIdx.x & 31;

    if (w < 3 * H) {
        int w0 = word[0];
        const float4* emb4 = (const float4*)(emb + (size_t)w0 * H);
        const float4* ctx4 = (const float4*)last_context;
        const float4* row = (const float4*)(W_ih0 + (size_t)w * (2 * H));
        float acc = 0.f;
        #pragma unroll
        for (int t = 0; t < 8; t++) {
            int i = lane + t * 32;
            float4 a = row[i];
            float4 x = emb4[i];
            acc += x.x * a.x + x.y * a.y + x.z * a.z + x.w * a.w;
        }
        #pragma unroll
        for (int t = 8; t < 16; t++) {
            int i = lane + t * 32;
            float4 a = row[i];
            float4 x = ctx4[i - 256];
            acc += x.x * a.x + x.y * a.y + x.z * a.z + x.w * a.w;
        }
        acc = warp_sum(acc);
        if (lane == 0) g_gi0[w] = acc + b_ih0[w];
    } else if (w < 6 * H) {
        int r = w - 3 * H;
        const float4* row = (const float4*)(W_hh0 + (size_t)r * H);
        const float4* hv = (const float4*)last_hidden;
        float acc = 0.f;
        #pragma unroll
        for (int t = 0; t < 8; t++) {
            int i = lane + t * 32;
            float4 a = row[i];
            float4 x = hv[i];
            acc += x.x * a.x + x.y * a.y + x.z * a.z + x.w * a.w;
        }
        acc = warp_sum(acc);
        if (lane == 0) g_gh0[r] = acc + b_hh0[r];
    } else {
        int r = w - 6 * H;
        const float4* row = (const float4*)(W_hh1 + (size_t)r * H);
        const float4* hv = (const float4*)(last_hidden + H);
        float acc = 0.f;
        #pragma unroll
        for (int t = 0; t < 8; t++) {
            int i = lane + t * 32;
            float4 a = row[i];
            float4 x = hv[i];
            acc += x.x * a.x + x.y * a.y + x.z * a.z + x.w * a.w;
        }
        acc = warp_sum(acc);
        if (lane == 0) g_gh1[r] = acc + b_hh1[r];
    }
}

// ---------------- GRU kernel B: one gate-row per warp (3072 warps) + in-block h1 combine ----------------
// 128 blocks x 768 threads (24 warps). Block b handles outputs j = b*8 .. b*8+7:
//   warps [0,8):   r-rows for the 8 outputs
//   warps [8,16):  z-rows
//   warps [16,24): n-rows
// Per-warp dot -> smem; 8 threads combine h1 (g_gh1 ready from k_gru_a). h0 combined per-block.
__global__ void k_gru_b(const float* __restrict__ W_ih1,
                        const float* __restrict__ b_ih1,
                        const float* __restrict__ last_hidden,
                        float* __restrict__ out_h0,
                        float* __restrict__ out_h1) {
    __shared__ __align__(16) float h0sh[H];
    __shared__ float gpart[24];
    int tid = threadIdx.x;  // 768
    int wid = tid >> 5;     // 0..23
    int lane = tid & 31;

    // h0 combine from L2-hot bias-folded partials
    for (int j = tid; j < H; j += 768) {
        float r = 1.f / (1.f + expf(-(g_gi0[j] + g_gh0[j])));
        float z = 1.f / (1.f + expf(-(g_gi0[j + H] + g_gh0[j + H])));
        float n = tanhf(g_gi0[j + 2 * H] + r * g_gh0[j + 2 * H]);
        float ho = (1.f - z) * n + z * last_hidden[j];
        h0sh[j] = ho;
        if (blockIdx.x == 0) out_h0[j] = ho;
    }
    __syncthreads();

    int local = wid & 7;   // output within block (0..7)
    int gate = wid >> 3;   // 0=r, 1=z, 2=n
    int j = blockIdx.x * 8 + local;
    const float4* row = (const float4*)(W_ih1 + (size_t)(j + gate * H) * H);
    const float4* xv = (const float4*)h0sh;
    float acc = 0.f;
    #pragma unroll
    for (int t = 0; t < 8; t++) {
        int i = lane + t * 32;
        float4 a = row[i];
        float4 x = xv[i];
        acc += x.x * a.x + x.y * a.y + x.z * a.z + x.w * a.w;
    }
    acc = warp_sum(acc);
    if (lane == 0) gpart[wid] = acc;
    __syncthreads();

    if (tid < 8) {
        int jj = blockIdx.x * 8 + tid;
        float ar = gpart[tid];
        float az = gpart[tid + 8];
        float an = gpart[tid + 16];
        float gr = ar + b_ih1[jj] + g_gh1[jj];
        float gz = az + b_ih1[jj + H] + g_gh1[jj + H];
        float r = 1.f / (1.f + expf(-gr));
        float z = 1.f / (1.f + expf(-gz));
        float n = tanhf(an + b_ih1[jj + 2 * H] + r * g_gh1[jj + 2 * H]);
        float h = (1.f - z) * n + z * last_hidden[H + jj];
        g_h1[jj] = h;
        out_h1[jj] = h;
    }
}

// ---------------- v partials: weighted row-sum of Wa (coalesced) ----------------
__global__ void k_v_part(const float* __restrict__ Wa) {
    __shared__ float hsh[16];
    int tid = threadIdx.x;  // 128
    int r0 = blockIdx.y * 16;
    if (tid < 16) hsh[tid] = g_h1[r0 + tid];
    __syncthreads();
    int j = blockIdx.x * 128 + tid;
    float a0 = 0.f, a1 = 0.f, a2 = 0.f, a3 = 0.f;
    #pragma unroll
    for (int ss = 0; ss < 16; ss += 4) {
        a0 += hsh[ss + 0] * Wa[(size_t)(r0 + ss + 0) * H + j];
        a1 += hsh[ss + 1] * Wa[(size_t)(r0 + ss + 1) * H + j];
        a2 += hsh[ss + 2] * Wa[(size_t)(r0 + ss + 2) * H + j];
        a3 += hsh[ss + 3] * Wa[(size_t)(r0 + ss + 3) * H + j];
    }
    g_vpart[blockIdx.y * H + j] = (a0 + a1) + (a2 + a3);
}

// ---------------- v = reduce(vpart) ; c = ba.h1 ----------------
__global__ void k_v_reduce(const float* __restrict__ ba) {
    int tid = threadIdx.x;  // 256
    if (blockIdx.x == 4) {
        float a = 0.f;
        for (int i = tid; i < H; i += 256) a += ba[i] * g_h1[i];
        a = warp_sum(a);
        __shared__ float red[8];
        if ((tid & 31) == 0) red[tid >> 5] = a;
        __syncthreads();
        if (tid == 0) {
            float s = 0.f;
            #pragma unroll
            for (int i = 0; i < 8; i++) s += red[i];
            g_c = s;
        }
        return;
    }
    int j = blockIdx.x * 256 + tid;
    float a = 0.f;
    #pragma unroll
    for (int y = 0; y < 64; y++) a += g_vpart[y * H + j];
    g_v[j] = a;
}

// ---------------- scores[s] = enc[s,:].v + c  (warp per s) ----------------
__global__ void k_scores(const float* __restrict__ enc) {
    int warp = (blockIdx.x * blockDim.x + threadIdx.x) >> 5;
    int lane = threadIdx.x & 31;
    if (warp >= SEQ) return;
    const float4* e = (const float4*)(enc + (size_t)warp * H);
    const float4* vv = (const float4*)g_v;
    float acc = 0.f;
    #pragma unroll
    for (int t = 0; t < H / 128; t++) {
        int i = lane + t * 32;
        float4 a = e[i];
        float4 b = vv[i];
        acc += a.x * b.x + a.y * b.y + a.z * b.z + a.w * b.w;
    }
    acc = warp_sum(acc);
    if (lane == 0) g_scores[warp] = acc + g_c;
}

// ---------------- softmax over 2048 scores (single block) ----------------
__global__ void k_softmax(float* __restrict__ out_attn) {
    __shared__ float red[32];
    __shared__ float bc;
    int tid = threadIdx.x;  // 1024

    float m = -1e30f;
    for (int s = tid; s < SEQ; s += 1024) m = fmaxf(m, g_scores[s]);
    m = warp_max(m);
    if ((tid & 31) == 0) red[tid >> 5] = m;
    __syncthreads();
    if (tid < 32) {
        float v = warp_max(red[tid]);
        if (tid == 0) bc = v;
    }
    __syncthreads();
    float M = bc;

    float sum = 0.f;
    for (int s = tid; s < SEQ; s += 1024) {
        float e = expf(g_scores[s] - M);
        g_attn[s] = e;
        sum += e;
    }
    sum = warp_sum(sum);
    if ((tid & 31) == 0) red[tid >> 5] = sum;
    __syncthreads();
    if (tid < 32) {
        float v = warp_sum(red[tid]);
        if (tid == 0) bc = 1.f / v;
    }
    __syncthreads();
    float inv = bc;
    for (int s = tid; s < SEQ; s += 1024) {
        float w = g_attn[s] * inv;
        g_attn[s] = w;
        out_attn[s] = w;
    }
}

// ---------------- context partials: 64 chunks of 32 rows (coalesced) ----------------
__global__ void k_ctx_part(const float* __restrict__ enc) {
    __shared__ float wsh[32];
    int tid = threadIdx.x;  // 128
    int s0 = blockIdx.y * 32;
    if (tid < 32) wsh[tid] = g_attn[s0 + tid];
    __syncthreads();
    int j = blockIdx.x * 128 + tid;
    float a0 = 0.f, a1 = 0.f, a2 = 0.f, a3 = 0.f;
    #pragma unroll
    for (int ss = 0; ss < 32; ss += 4) {
        a0 += wsh[ss + 0] * enc[(size_t)(s0 + ss + 0) * H + j];
        a1 += wsh[ss + 1] * enc[(size_t)(s0 + ss + 1) * H + j];
        a2 += wsh[ss + 2] * enc[(size_t)(s0 + ss + 2) * H + j];
        a3 += wsh[ss + 3] * enc[(size_t)(s0 + ss + 3) * H + j];
    }
    g_cpart[blockIdx.y * H + j] = (a0 + a1) + (a2 + a3);
}

// ---------------- reduce 64 partials -> context ----------------
__global__ void k_ctx_reduce(float* __restrict__ out_context) {
    int j = blockIdx.x * blockDim.x + threadIdx.x;
    if (j >= H) return;
    float a = 0.f;
    #pragma unroll
    for (int y = 0; y < 64; y++) a += g_cpart[y * H + j];
    g_context[j] = a;
    out_context[j] = a;
}

// ---------------- logits pass A: W_out[:, :H] @ h1 + b_out -> g_logits ----------------
__global__ void k_logits_h1(const float* __restrict__ W_out, const float* __restrict__ b_out) {
    __shared__ __align__(16) float u[H];
    for (int k = threadIdx.x; k < H; k += 256) u[k] = g_h1[k];
    __syncthreads();

    int r = blockIdx.x * 8 + (threadIdx.x >> 5);
    if (r >= VOC) return;
    int lane = threadIdx.x & 31;
    const float4* w = (const float4*)(W_out + (size_t)r * (2 * H));
    const float4* uv = (const float4*)u;
    float acc0 = 0.f, acc1 = 0.f;
    #pragma unroll
    for (int t = 0; t < 4; t++) {
        int i0 = lane + (2 * t) * 32;
        int i1 = lane + (2 * t + 1) * 32;
        float4 a = __ldcs(&w[i0]);
        float4 b = uv[i0];
        acc0 += a.x * b.x + a.y * b.y + a.z * b.z + a.w * b.w;
        float4 c = __ldcs(&w[i1]);
        float4 d = uv[i1];
        acc1 += c.x * d.x + c.y * d.y + c.z * d.z + c.w * d.w;
    }
    float acc = warp_sum(acc0 + acc1);
    if (lane == 0) g_logits[r] = acc + b_out[r];
}

// ---------------- logits pass B: W_out[:, H:] @ context -> g_logits2 ----------------
__global__ void k_logits_ctx(const float* __restrict__ W_out) {
    __shared__ __align__(16) float u[H];
    for (int k = threadIdx.x; k < H; k += 256) u[k] = g_context[k];
    __syncthreads();

    int r = blockIdx.x * 8 + (threadIdx.x >> 5);
    if (r >= VOC) return;
    int lane = threadIdx.x & 31;
    const float4* w = (const float4*)(W_out + (size_t)r * (2 * H) + H);
    const float4* uv = (const float4*)u;
    float acc0 = 0.f, acc1 = 0.f;
    #pragma unroll
    for (int t = 0; t < 4; t++) {
        int i0 = lane + (2 * t) * 32;
        int i1 = lane + (2 * t + 1) * 32;
        float4 a = __ldcs(&w[i0]);
        float4 b = uv[i0];
        acc0 += a.x * b.x + a.y * b.y + a.z * b.z + a.w * b.w;
        float4 c = __ldcs(&w[i1]);
        float4 d = uv[i1];
        acc1 += c.x * d.x + c.y * d.y + c.z * d.z + c.w * d.w;
    }
    float acc = warp_sum(acc0 + acc1);
    if (lane == 0) g_logits2[r] = acc;
}

// ---------------- fused lse + output: 32 resident blocks, ticket + flag ----------------
__global__ void k_lse_out(float* __restrict__ out) {
    __shared__ float red[8];
    __shared__ float bc;
    int tid = threadIdx.x;  // 256
    const int chunk = (VOC + LSE_BLOCKS - 1) / LSE_BLOCKS;
    int lo = blockIdx.x * chunk;
    int hi = min(lo + chunk, VOC);

    float m = -1e30f;
    for (int r = lo + tid; r < hi; r += 256) m = fmaxf(m, g_logits[r] + g_logits2[r]);
    m = warp_max(m);
    if ((tid & 31) == 0) red[tid >> 5] = m;
    __syncthreads();
    if (tid < 32) {
        float v = (tid < 8) ? red[tid] : -1e30f;
        v = warp_max(v);
        if (tid == 0) bc = v;
    }
    __syncthreads();
    float M = bc;

    float sum = 0.f;
    for (int r = lo + tid; r < hi; r += 256) sum += expf(g_logits[r] + g_logits2[r] - M);
    sum = warp_sum(sum);
    if ((tid & 31) == 0) red[tid >> 5] = sum;
    __syncthreads();
    if (tid < 32) {
        float v = (tid < 8) ? red[tid] : 0.f;
        v = warp_sum(v);
        if (tid == 0) {
            g_lse_m[blockIdx.x] = M;
            g_lse_s[blockIdx.x] = v;
        }
    }

    __threadfence();
    __syncthreads();
    if (tid == 0) {
        unsigned t = atomicAdd(&g_cnt, 1u);
        if (t == LSE_BLOCKS - 1) {
            __threadfence();
            float Mg = -1e30f;
            #pragma unroll
            for (int i = 0; i < LSE_BLOCKS; i++) Mg = fmaxf(Mg, g_lse_m[i]);
            float Z = 0.f;
            #pragma unroll
            for (int i = 0; i < LSE_BLOCKS; i++) Z += g_lse_s[i] * expf(g_lse_m[i] - Mg);
            g_logZ = Mg + logf(Z);
            __threadfence();
            atomicExch(&g_flag, 1u);
        }
        while (atomicAdd(&g_flag, 0u) == 0u) { __nanosleep(64); }
    }
    __syncthreads();
    __threadfence();
    float lz = g_logZ;

    for (int r = lo + tid; r < hi; r += 256) {
        out[r] = g_logits[r] + g_logits2[r] - lz;
    }

    __syncthreads();
    if (tid == 0) {
        __threadfence();
        unsigned d = atomicAdd(&g_done, 1u);
        if (d == LSE_BLOCKS - 1) {
            g_cnt = 0;
            g_done = 0;
            g_flag = 0;
        }
    }
}

// ---------------- stream/event setup (static ctor: pre-baseline, pre-capture) ----------------
static cudaStream_t g_s1;
static cudaEvent_t g_e1, g_e2;

namespace {
struct StreamInit {
    StreamInit() {
        cudaStreamCreateWithFlags(&g_s1, cudaStreamNonBlocking);
        cudaEventCreateWithFlags(&g_e1, cudaEventDisableTiming);
        cudaEventCreateWithFlags(&g_e2, cudaEventDisableTiming);
        k_warm<<<1, 32>>>();
        k_warm<<<1, 32, 0, g_s1>>>();
        cudaEventRecord(g_e1, 0);
        cudaEventRecord(g_e2, g_s1);
        cudaDeviceSynchronize();
    }
};
StreamInit g_stream_init;
}

// ---------------- launch ----------------
extern "C" void kernel_launch(void* const* d_in, const int* in_sizes, int n_in,
                              void* d_out, int out_size) {
    const int*   word         = (const int*)  d_in[0];
    const float* last_context = (const float*)d_in[1];
    const float* last_hidden  = (const float*)d_in[2];
    const float* enc          = (const float*)d_in[3];
    const float* emb          = (const float*)d_in[4];
    const float* W_ih0        = (const float*)d_in[5];
    const float* W_hh0        = (const float*)d_in[6];
    const float* b_ih0        = (const float*)d_in[7];
    const float* b_hh0        = (const float*)d_in[8];
    const float* W_ih1        = (const float*)d_in[9];
    const float* W_hh1        = (const float*)d_in[10];
    const float* b_ih1        = (const float*)d_in[11];
    const float* b_hh1        = (const float*)d_in[12];
    const float* Wa           = (const float*)d_in[13];
    const float* ba           = (const float*)d_in[14];
    const float* W_out        = (const float*)d_in[15];
    const float* b_out        = (const float*)d_in[16];
    float* out = (float*)d_out;

    // d_out layout: [output VOC | context H | hidden 2H | attn SEQ]
    float* out_context = out + VOC;
    float* out_h0      = out + VOC + H;
    float* out_h1      = out + VOC + 2 * H;
    float* out_attn    = out + VOC + 3 * H;

    // GRU chain: 2 serial kernels; gru_b emits h0 AND h1 (one gate-row per warp)
    k_gru_a<<<1152, 256>>>(word, emb, last_context, W_ih0, W_hh0, W_hh1,
                           last_hidden, b_ih0, b_hh0, b_hh1);
    k_gru_b<<<128, 768>>>(W_ih1, b_ih1, last_hidden, out_h0, out_h1);

    // Fork: attention chain + logits_ctx on side stream (g_h1 materialized by gru_b)
    cudaEventRecord(g_e1, 0);
    cudaStreamWaitEvent(g_s1, g_e1, 0);

    {
        dim3 g(8, 64);
        k_v_part<<<g, 128, 0, g_s1>>>(Wa);
    }
    k_v_reduce<<<5, 256, 0, g_s1>>>(ba);
    k_scores<<<SEQ / 8, 256, 0, g_s1>>>(enc);
    k_softmax<<<1, 1024, 0, g_s1>>>(out_attn);
    {
        dim3 g(8, 64);
        k_ctx_part<<<g, 128, 0, g_s1>>>(enc);
    }
    k_ctx_reduce<<<4, 256, 0, g_s1>>>(out_context);
    k_logits_ctx<<<(VOC + 7) / 8, 256, 0, g_s1>>>(W_out);
    cudaEventRecord(g_e2, g_s1);

    // Main stream: logits pass A starts right after gru_b
    k_logits_h1<<<(VOC + 7) / 8, 256>>>(W_out, b_out);

    // Join, then fused log-softmax + output
    cudaStreamWaitEvent(0, g_e2, 0);
    k_lse_out<<<LSE_BLOCKS, 256>>>(out);
}